// round 9
// baseline (speedup 1.0000x reference)
#include <cuda_runtime.h>
#include <cstdint>

// ---------------- problem constants ----------------
#define BB 16
#define TT 250
#define EE 512
#define HH 1024
#define VV 32000
#define H3 3072
#define MM (BB*TT)          // 4000

// ---------------- scratch (static device memory; no allocations) ----------------
__device__ __align__(16) float g_xproj[MM*H3];        // [4000,3072]
__device__ __align__(16) float g_hs[MM*HH];           // [4000,1024] tf32-rounded
__device__ __align__(16) float g_h[2][BB*HH];         // double-buffered hidden state
__device__ __align__(16) float g_embR[(size_t)VV*EE]; // emb, tf32-rounded
__device__ __align__(16) float g_WR [EE*H3];          // W,   tf32-rounded
__device__ __align__(16) float g_WoR[(size_t)HH*VV];  // Wo,  tf32-rounded
__device__ unsigned g_cnt = 0;
__device__ unsigned g_sense = 0;

// ---------------- helpers ----------------
__device__ __forceinline__ unsigned f2tf(float f){
    unsigned u; asm("cvt.rna.tf32.f32 %0, %1;" : "=r"(u) : "f"(f)); return u;
}
__device__ __forceinline__ void mma_tf32(float* c,
    unsigned a0, unsigned a1, unsigned a2, unsigned a3,
    unsigned b0, unsigned b1){
    asm volatile("mma.sync.aligned.m16n8k8.row.col.f32.tf32.tf32.f32 "
        "{%0,%1,%2,%3},{%4,%5,%6,%7},{%8,%9},{%0,%1,%2,%3};"
        : "+f"(c[0]), "+f"(c[1]), "+f"(c[2]), "+f"(c[3])
        : "r"(a0), "r"(a1), "r"(a2), "r"(a3), "r"(b0), "r"(b1));
}
__device__ __forceinline__ uint32_t smem_u32(const void* p){
    uint32_t a;
    asm("{ .reg .u64 t; cvta.to.shared.u64 t, %1; cvt.u32.u64 %0, t; }" : "=r"(a) : "l"(p));
    return a;
}
__device__ __forceinline__ void cpa16(uint32_t dst, const void* src, int sz){
    asm volatile("cp.async.cg.shared.global [%0], [%1], 16, %2;" :: "r"(dst), "l"(src), "r"(sz));
}
__device__ __forceinline__ void cpa_commit(){ asm volatile("cp.async.commit_group;"); }
template<int N> __device__ __forceinline__ void cpa_wait(){ asm volatile("cp.async.wait_group %0;" :: "n"(N)); }

// =====================================================================
// Elementwise tf32 pre-round: dst[i] = rna_tf32(src[i]).  n % 4 == 0.
// =====================================================================
__global__ void round_tf32(const float* __restrict__ src, float* __restrict__ dst, size_t n)
{
    size_t stride = (size_t)gridDim.x * blockDim.x * 4;
    for (size_t i = ((size_t)blockIdx.x * blockDim.x + threadIdx.x) * 4; i < n; i += stride){
        float4 v = *reinterpret_cast<const float4*>(src + i);
        v.x = __uint_as_float(f2tf(v.x));
        v.y = __uint_as_float(f2tf(v.y));
        v.z = __uint_as_float(f2tf(v.z));
        v.w = __uint_as_float(f2tf(v.w));
        *reinterpret_cast<float4*>(dst + i) = v;
    }
}

// =====================================================================
// 4-stage cp.async pipelined tf32 GEMM:  C[M,N] = A[M,K] @ B[K,N] + bias[N]
// BM=128, BN=128, BK=32, *512 threads*, 16 warps (4x4), warp tile 32x32.
// 16 warps/SM (4 per SMSP) to cover LDS/HMMA latency (R8 showed 2 warps/SMSP
// is latency-starved: all pipes < 40%).
// Operands must be PRE-ROUNDED to tf32 (cp.async cannot convert).
// GATHER: A row m comes from A[tokens[m]] (embedding, K = E).
// =====================================================================
#define BM 128
#define BN 128
#define BK 32
#define NTHR 512
#define AS_LD 36      // BK + 4 pad  (conflict-free A frags)
#define BS_LD 136     // BN + 8 pad  (conflict-free B frags)
#define STG_F (BM*AS_LD + BK*BS_LD)          // 8960 floats per stage
#define GEMM_SMEM (4*STG_F*4)                // 143360 bytes

template<bool GATHER>
__global__ __launch_bounds__(NTHR, 1)
void gemm_pipe(const float* __restrict__ A, const float* __restrict__ B,
               const float* __restrict__ bias, float* __restrict__ C,
               int M, int N, int K, const int* __restrict__ tokens)
{
    extern __shared__ float sm[];
    const uint32_t sb = smem_u32(sm);

    const int tid  = threadIdx.x;
    const int lane = tid & 31;
    const int w    = tid >> 5;         // 0..15
    const int g    = lane >> 2;        // 0..7
    const int a    = lane & 3;         // 0..3
    const int wm   = (w >> 2) * 32;    // warp row offset (4 rows of warps)
    const int wn   = (w & 3) * 32;     // warp col offset (4 cols of warps)

    const int bm = blockIdx.x * BM;    // m fastest -> blocks in a wave share B tiles via L2
    const int bn = blockIdx.y * BN;
    const int KT = K / BK;

    float acc[2][4][4];
    #pragma unroll
    for (int i = 0; i < 2; i++)
        #pragma unroll
        for (int j = 0; j < 4; j++)
            #pragma unroll
            for (int q = 0; q < 4; q++) acc[i][j][q] = 0.f;

    // ---- issue one k-tile stage of cp.async (A: 1024 chunks, B: 1024 chunks) ----
    auto issue = [&](int kt){
        const int s = kt & 3;
        const uint32_t Ab = sb + s*STG_F*4;
        const uint32_t Bb = Ab + BM*AS_LD*4;
        const int k0 = kt * BK;
        #pragma unroll
        for (int i = 0; i < 2; i++){
            int idx = tid + i*NTHR;            // 0..1023
            int row = idx >> 3, c4 = (idx & 7)*4;
            int m = bm + row;
            const float* src = A;
            int sz = 0;
            if (GATHER){
                if (m < M){ int tok = __ldg(&tokens[m]);
                            src = A + (size_t)tok*K + k0 + c4; sz = 16; }
            } else {
                if (m < M){ src = A + (size_t)m*K + k0 + c4; sz = 16; }
            }
            cpa16(Ab + (row*AS_LD + c4)*4, src, sz);
        }
        #pragma unroll
        for (int i = 0; i < 2; i++){
            int idx = tid + i*NTHR;            // 0..1023
            int row = idx >> 5, c4 = (idx & 31)*4;
            const float* src = B + (size_t)(k0 + row)*N + bn + c4;
            cpa16(Bb + (row*BS_LD + c4)*4, src, 16);
        }
    };

    // ---- compute one staged k-tile ----
    auto compute = [&](int s){
        const float* Ab  = sm + s*STG_F;
        const float* Bb2 = Ab + BM*AS_LD;
        #pragma unroll
        for (int ks = 0; ks < 4; ks++){
            const int kk = ks*8;
            unsigned Af[2][4];
            #pragma unroll
            for (int mt = 0; mt < 2; mt++){
                const float* ap = Ab + (wm + mt*16)*AS_LD + kk;
                Af[mt][0] = __float_as_uint(ap[(g    )*AS_LD + a    ]);
                Af[mt][1] = __float_as_uint(ap[(g + 8)*AS_LD + a    ]);
                Af[mt][2] = __float_as_uint(ap[(g    )*AS_LD + a + 4]);
                Af[mt][3] = __float_as_uint(ap[(g + 8)*AS_LD + a + 4]);
            }
            #pragma unroll
            for (int nt = 0; nt < 4; nt++){
                const float* bp = Bb2 + kk*BS_LD + wn + nt*8 + g;
                unsigned b0 = __float_as_uint(bp[(a    )*BS_LD]);
                unsigned b1 = __float_as_uint(bp[(a + 4)*BS_LD]);
                mma_tf32(acc[0][nt], Af[0][0],Af[0][1],Af[0][2],Af[0][3], b0, b1);
                mma_tf32(acc[1][nt], Af[1][0],Af[1][1],Af[1][2],Af[1][3], b0, b1);
            }
        }
    };

    // ---- pipeline: 3 stages in flight; exactly one commit per loop iter ----
    issue(0); cpa_commit();
    issue(1); cpa_commit();
    issue(2); cpa_commit();
    for (int kt = 0; kt < KT; kt++){
        cpa_wait<2>();          // stage kt's group complete
        __syncthreads();        // make it visible block-wide
        compute(kt & 3);
        __syncthreads();        // everyone done reading stage kt
        if (kt + 3 < KT) issue(kt + 3);
        cpa_commit();           // uniform group count (may be empty)
    }

    // ---- epilogue: +bias, write float2 pairs ----
    #pragma unroll
    for (int mt = 0; mt < 2; mt++){
        #pragma unroll
        for (int nt = 0; nt < 4; nt++){
            int col  = bn + wn + nt*8 + 2*a;
            float bz0 = __ldg(&bias[col]);
            float bz1 = __ldg(&bias[col+1]);
            int row0 = bm + wm + mt*16 + g;
            if (row0 < M){
                float2 v = make_float2(acc[mt][nt][0] + bz0, acc[mt][nt][1] + bz1);
                *reinterpret_cast<float2*>(&C[(size_t)row0*N + col]) = v;
            }
            int row1 = row0 + 8;
            if (row1 < M){
                float2 v = make_float2(acc[mt][nt][2] + bz0, acc[mt][nt][3] + bz1);
                *reinterpret_cast<float2*>(&C[(size_t)row1*N + col]) = v;
            }
        }
    }
}

// =====================================================================
// Persistent GRU scan kernel (proven in R2). 128 blocks, 256 threads.
// Block owns 8 hidden cols; U slice tf32-rounded in SMEM for all steps.
// hi/lo tf32 split of h keeps the recurrence ~fp32 accurate.
// Stores hs tf32-pre-rounded (A operand of GEMM3).
// =====================================================================
#define SCAN_NBLK 128
#define U_LD 26
#define H_LD 1028
#define SCAN_SMEM ((HH*U_LD + BB*H_LD + 8*3*BB*8)*4)

__global__ __launch_bounds__(256, 1)
void gru_scan_kernel(const float* __restrict__ xproj,
                     const float* __restrict__ h0,
                     const float* __restrict__ U,
                     const float* __restrict__ brec)
{
    extern __shared__ float sm[];
    float* U_s = sm;
    float* h_s = sm + HH*U_LD;
    float* red = h_s + BB*H_LD;
    __shared__ unsigned bar_phase;

    const int tid  = threadIdx.x;
    const int lane = tid & 31;
    const int w    = tid >> 5;
    const int g    = lane >> 2;
    const int a    = lane & 3;
    const int j0   = blockIdx.x * 8;

    if (tid == 0) bar_phase = 0;

    for (int e = tid; e < HH*24; e += 256){
        int k = e / 24, c = e - k*24;
        int gate = c >> 3, jj = c & 7;
        float v = U[(size_t)k*H3 + gate*HH + j0 + jj];
        U_s[k*U_LD + c] = __uint_as_float(f2tf(v));
    }
    __syncthreads();

    for (int t = 0; t < TT; t++){
        const float* hsrc = (t == 0) ? h0 : g_h[(t-1) & 1];
        #pragma unroll
        for (int i = 0; i < 16; i++){
            int e = (i*256 + tid)*4;
            int b = e >> 10, k = e & 1023;
            float4 v = *reinterpret_cast<const float4*>(hsrc + e);
            *reinterpret_cast<float4*>(&h_s[b*H_LD + k]) = v;
        }
        __syncthreads();

        float c[3][4];
        #pragma unroll
        for (int nt = 0; nt < 3; nt++)
            #pragma unroll
            for (int q = 0; q < 4; q++) c[nt][q] = 0.f;

        const int kbase = w * 128;
        #pragma unroll 4
        for (int ks = 0; ks < 16; ks++){
            int k = kbase + ks*8;
            float f0 = h_s[(g    )*H_LD + k + a    ];
            float f1 = h_s[(g + 8)*H_LD + k + a    ];
            float f2 = h_s[(g    )*H_LD + k + a + 4];
            float f3 = h_s[(g + 8)*H_LD + k + a + 4];
            unsigned h0b = f2tf(f0), h1b = f2tf(f1), h2b = f2tf(f2), h3b = f2tf(f3);
            unsigned l0 = f2tf(f0 - __uint_as_float(h0b));
            unsigned l1 = f2tf(f1 - __uint_as_float(h1b));
            unsigned l2 = f2tf(f2 - __uint_as_float(h2b));
            unsigned l3 = f2tf(f3 - __uint_as_float(h3b));
            #pragma unroll
            for (int nt = 0; nt < 3; nt++){
                unsigned b0 = __float_as_uint(U_s[(k + a    )*U_LD + nt*8 + g]);
                unsigned b1 = __float_as_uint(U_s[(k + a + 4)*U_LD + nt*8 + g]);
                mma_tf32(c[nt], h0b, h1b, h2b, h3b, b0, b1);
                mma_tf32(c[nt], l0,  l1,  l2,  l3,  b0, b1);
            }
        }

        #pragma unroll
        for (int nt = 0; nt < 3; nt++){
            float* r = red + ((w*3 + nt)*BB)*8;
            r[(g    )*8 + 2*a    ] = c[nt][0];
            r[(g    )*8 + 2*a + 1] = c[nt][1];
            r[(g + 8)*8 + 2*a    ] = c[nt][2];
            r[(g + 8)*8 + 2*a + 1] = c[nt][3];
        }
        __syncthreads();

        if (tid < 128){
            int b = tid >> 3, jj = tid & 7;
            float rec[3];
            #pragma unroll
            for (int nt = 0; nt < 3; nt++){
                float s = __ldg(&brec[nt*HH + j0 + jj]);
                #pragma unroll
                for (int ww = 0; ww < 8; ww++)
                    s += red[((ww*3 + nt)*BB + b)*8 + jj];
                rec[nt] = s;
            }
            size_t base = (size_t)(b*TT + t) * H3;
            float xz = xproj[base +          j0 + jj];
            float xr = xproj[base +   HH   + j0 + jj];
            float xh = xproj[base + 2*HH   + j0 + jj];
            float z  = 1.f / (1.f + expf(-(xz + rec[0])));
            float r  = 1.f / (1.f + expf(-(xr + rec[1])));
            float hh = tanhf(xh + r * rec[2]);
            float hold = h_s[b*H_LD + j0 + jj];
            float hn = z * hold + (1.f - z) * hh;
            g_h[t & 1][b*HH + j0 + jj] = hn;
            g_hs[(size_t)(b*TT + t)*HH + j0 + jj] = __uint_as_float(f2tf(hn));
        }

        __syncthreads();
        if (tid == 0){
            unsigned exp = bar_phase ^ 1u;
            __threadfence();
            if (atomicAdd(&g_cnt, 1u) == SCAN_NBLK - 1){
                atomicExch(&g_cnt, 0u);
                __threadfence();
                atomicExch(&g_sense, exp);
            } else {
                while (atomicAdd(&g_sense, 0u) != exp) { __nanosleep(64); }
            }
            __threadfence();
            bar_phase = exp;
        }
        __syncthreads();
    }
}

// =====================================================================
// host launcher
// =====================================================================
extern "C" void kernel_launch(void* const* d_in, const int* in_sizes, int n_in,
                              void* d_out, int out_size)
{
    const int*   tok  = (const int*)  d_in[0];   // [16,250]
    const float* h0   = (const float*)d_in[1];   // [16,1024]
    const float* emb  = (const float*)d_in[2];   // [32000,512]
    const float* W    = (const float*)d_in[3];   // [512,3072]
    const float* U    = (const float*)d_in[4];   // [1024,3072]
    const float* b    = (const float*)d_in[5];   // [2,3072]
    const float* Wo   = (const float*)d_in[6];   // [1024,32000]
    const float* bo   = (const float*)d_in[7];   // [32000]
    float* out = (float*)d_out;                  // [16,250,32000] f32

    float* xproj; cudaGetSymbolAddress((void**)&xproj, g_xproj);
    float* hs;    cudaGetSymbolAddress((void**)&hs,    g_hs);
    float* embR;  cudaGetSymbolAddress((void**)&embR,  g_embR);
    float* WR;    cudaGetSymbolAddress((void**)&WR,    g_WR);
    float* WoR;   cudaGetSymbolAddress((void**)&WoR,   g_WoR);

    cudaFuncSetAttribute(gemm_pipe<true>,
        cudaFuncAttributeMaxDynamicSharedMemorySize, GEMM_SMEM);
    cudaFuncSetAttribute(gemm_pipe<false>,
        cudaFuncAttributeMaxDynamicSharedMemorySize, GEMM_SMEM);
    cudaFuncSetAttribute(gru_scan_kernel,
        cudaFuncAttributeMaxDynamicSharedMemorySize, SCAN_SMEM);

    // 0) tf32 pre-round of GEMM operands (cp.async cannot convert)
    round_tf32<<<1184, 256>>>(emb, embR, (size_t)VV*EE);
    round_tf32<<<1184, 256>>>(W,   WR,   (size_t)EE*H3);
    round_tf32<<<1184, 256>>>(Wo,  WoR,  (size_t)HH*VV);

    // 1) x_proj = gather(embR, tokens) @ WR + b[0]
    {
        dim3 grid((MM + BM - 1)/BM, H3/BN);   // 32 x 24
        gemm_pipe<true><<<grid, NTHR, GEMM_SMEM>>>(embR, WR, b, xproj, MM, H3, EE, tok);
    }

    // 2) GRU scan over T=250
    gru_scan_kernel<<<SCAN_NBLK, 256, SCAN_SMEM>>>(xproj, h0, U, b + H3);

    // 3) logits = hs @ WoR + bo
    {
        dim3 grid((MM + BM - 1)/BM, VV/BN);   // 32 x 250
        gemm_pipe<false><<<grid, NTHR, GEMM_SMEM>>>(hs, WoR, bo, out, MM, VV, HH, nullptr);
    }
}

// round 10
// speedup vs baseline: 1.1624x; 1.1624x over previous
#include <cuda_runtime.h>
#include <cstdint>

// ---------------- problem constants ----------------
#define BB 16
#define TT 250
#define EE 512
#define HH 1024
#define VV 32000
#define H3 3072
#define MM (BB*TT)          // 4000

// ---------------- scratch (static device memory; no allocations) ----------------
__device__ __align__(16) float g_xproj[MM*H3];        // [4000,3072]
__device__ __align__(16) float g_hs[MM*HH];           // [4000,1024] tf32-rounded
__device__ __align__(16) float g_h[2][BB*HH];         // double-buffered hidden state
__device__ __align__(16) float g_embR[(size_t)VV*EE]; // emb, tf32-rounded
__device__ __align__(16) float g_WR [EE*H3];          // W,   tf32-rounded
__device__ __align__(16) float g_WoR[(size_t)HH*VV];  // Wo,  tf32-rounded
__device__ unsigned g_cnt = 0;
__device__ unsigned g_sense = 0;

// ---------------- helpers ----------------
__device__ __forceinline__ unsigned f2tf(float f){
    unsigned u; asm("cvt.rna.tf32.f32 %0, %1;" : "=r"(u) : "f"(f)); return u;
}
__device__ __forceinline__ void mma_tf32(float* c,
    unsigned a0, unsigned a1, unsigned a2, unsigned a3,
    unsigned b0, unsigned b1){
    asm volatile("mma.sync.aligned.m16n8k8.row.col.f32.tf32.tf32.f32 "
        "{%0,%1,%2,%3},{%4,%5,%6,%7},{%8,%9},{%0,%1,%2,%3};"
        : "+f"(c[0]), "+f"(c[1]), "+f"(c[2]), "+f"(c[3])
        : "r"(a0), "r"(a1), "r"(a2), "r"(a3), "r"(b0), "r"(b1));
}
__device__ __forceinline__ uint32_t smem_u32(const void* p){
    uint32_t a;
    asm("{ .reg .u64 t; cvta.to.shared.u64 t, %1; cvt.u32.u64 %0, t; }" : "=r"(a) : "l"(p));
    return a;
}
__device__ __forceinline__ void cpa16(uint32_t dst, const void* src, int sz){
    asm volatile("cp.async.cg.shared.global [%0], [%1], 16, %2;" :: "r"(dst), "l"(src), "r"(sz));
}
__device__ __forceinline__ void cpa_commit(){ asm volatile("cp.async.commit_group;"); }
template<int N> __device__ __forceinline__ void cpa_wait(){ asm volatile("cp.async.wait_group %0;" :: "n"(N)); }

// =====================================================================
// Elementwise tf32 pre-round: dst[i] = rna_tf32(src[i]).  n % 4 == 0.
// =====================================================================
__global__ void round_tf32(const float* __restrict__ src, float* __restrict__ dst, size_t n)
{
    size_t stride = (size_t)gridDim.x * blockDim.x * 4;
    for (size_t i = ((size_t)blockIdx.x * blockDim.x + threadIdx.x) * 4; i < n; i += stride){
        float4 v = *reinterpret_cast<const float4*>(src + i);
        v.x = __uint_as_float(f2tf(v.x));
        v.y = __uint_as_float(f2tf(v.y));
        v.z = __uint_as_float(f2tf(v.z));
        v.w = __uint_as_float(f2tf(v.w));
        *reinterpret_cast<float4*>(dst + i) = v;
    }
}

// =====================================================================
// 3-stage cp.async pipelined tf32 GEMM, 2 blocks/SM:
//   C[M,N] = A[M,K] @ B[K,N] + bias[N]
// BM=128, BN=128, BK=32, 256 threads, 8 warps (2x4), warp tile 64x32.
// One __syncthreads per k-tile. Two co-resident blocks form independent
// barrier domains so the SM always has issuable warps (R9 showed issue
// throughput scales with warps; this adds warps WITHOUT adding LDS).
// Operands must be PRE-ROUNDED to tf32 (cp.async cannot convert).
// GATHER: A row m comes from A[tokens[m]] (embedding, K = E).
// =====================================================================
#define BM 128
#define BN 128
#define BK 32
#define NTHR 256
#define AS_LD 36      // BK + 4 pad  (conflict-free A frags)
#define BS_LD 136     // BN + 8 pad  (conflict-free B frags)
#define STG_F (BM*AS_LD + BK*BS_LD)          // 8960 floats per stage
#define GEMM_SMEM (3*STG_F*4)                // 107520 bytes (2 blocks fit per SM)

template<bool GATHER>
__global__ __launch_bounds__(NTHR, 2)
void gemm_pipe(const float* __restrict__ A, const float* __restrict__ B,
               const float* __restrict__ bias, float* __restrict__ C,
               int M, int N, int K, const int* __restrict__ tokens)
{
    extern __shared__ float sm[];
    const uint32_t sb = smem_u32(sm);

    const int tid  = threadIdx.x;
    const int lane = tid & 31;
    const int w    = tid >> 5;         // 0..7
    const int g    = lane >> 2;        // 0..7
    const int a    = lane & 3;         // 0..3
    const int wm   = (w >> 2) * 64;    // warp row offset (2 row-groups of 64)
    const int wn   = (w & 3) * 32;     // warp col offset (4 col-groups of 32)

    const int bm = blockIdx.x * BM;    // m fastest -> co-resident blocks share B tiles via L2
    const int bn = blockIdx.y * BN;
    const int KT = K / BK;

    float acc[4][4][4];
    #pragma unroll
    for (int i = 0; i < 4; i++)
        #pragma unroll
        for (int j = 0; j < 4; j++)
            #pragma unroll
            for (int q = 0; q < 4; q++) acc[i][j][q] = 0.f;

    // ---- issue one k-tile stage of cp.async (A: 1024 chunks, B: 1024 chunks) ----
    auto issue = [&](int kt, int s){
        const uint32_t Ab = sb + s*STG_F*4;
        const uint32_t Bb = Ab + BM*AS_LD*4;
        const int k0 = kt * BK;
        #pragma unroll
        for (int i = 0; i < 4; i++){
            int idx = tid + i*NTHR;            // 0..1023
            int row = idx >> 3, c4 = (idx & 7)*4;
            int m = bm + row;
            const float* src = A;
            int sz = 0;
            if (GATHER){
                if (m < M){ int tok = __ldg(&tokens[m]);
                            src = A + (size_t)tok*K + k0 + c4; sz = 16; }
            } else {
                if (m < M){ src = A + (size_t)m*K + k0 + c4; sz = 16; }
            }
            cpa16(Ab + (row*AS_LD + c4)*4, src, sz);
        }
        #pragma unroll
        for (int i = 0; i < 4; i++){
            int idx = tid + i*NTHR;            // 0..1023
            int row = idx >> 5, c4 = (idx & 31)*4;
            const float* src = B + (size_t)(k0 + row)*N + bn + c4;
            cpa16(Bb + (row*BS_LD + c4)*4, src, 16);
        }
    };

    // ---- compute one staged k-tile ----
    auto compute = [&](int s){
        const float* Ab  = sm + s*STG_F;
        const float* Bb2 = Ab + BM*AS_LD;
        #pragma unroll
        for (int ks = 0; ks < 4; ks++){
            const int kk = ks*8;
            unsigned Af[4][4];
            #pragma unroll
            for (int mt = 0; mt < 4; mt++){
                const float* ap = Ab + (wm + mt*16)*AS_LD + kk;
                Af[mt][0] = __float_as_uint(ap[(g    )*AS_LD + a    ]);
                Af[mt][1] = __float_as_uint(ap[(g + 8)*AS_LD + a    ]);
                Af[mt][2] = __float_as_uint(ap[(g    )*AS_LD + a + 4]);
                Af[mt][3] = __float_as_uint(ap[(g + 8)*AS_LD + a + 4]);
            }
            #pragma unroll
            for (int nt = 0; nt < 4; nt++){
                const float* bp = Bb2 + kk*BS_LD + wn + nt*8 + g;
                unsigned b0 = __float_as_uint(bp[(a    )*BS_LD]);
                unsigned b1 = __float_as_uint(bp[(a + 4)*BS_LD]);
                #pragma unroll
                for (int mt = 0; mt < 4; mt++)
                    mma_tf32(acc[mt][nt], Af[mt][0],Af[mt][1],Af[mt][2],Af[mt][3], b0, b1);
            }
        }
    };

    // ---- 3-stage pipeline, ONE barrier per k-tile ----
    // iter kt: wait(group kt) ; BAR (=> all finished compute(kt-1), stage
    // (kt+2)%3 == (kt-1)%3 is free, and stage kt is visible) ; issue(kt+2) ;
    // compute(kt).
    issue(0, 0); cpa_commit();
    issue(1, 1); cpa_commit();
    int s_c = 0, s_i = 2;
    for (int kt = 0; kt < KT; kt++){
        cpa_wait<1>();
        __syncthreads();
        if (kt + 2 < KT) issue(kt + 2, s_i);
        cpa_commit();           // uniform group count (may be empty)
        compute(s_c);
        s_c = (s_c == 2) ? 0 : s_c + 1;
        s_i = (s_i == 2) ? 0 : s_i + 1;
    }

    // ---- epilogue: +bias, write float2 pairs ----
    #pragma unroll
    for (int mt = 0; mt < 4; mt++){
        #pragma unroll
        for (int nt = 0; nt < 4; nt++){
            int col  = bn + wn + nt*8 + 2*a;
            float bz0 = __ldg(&bias[col]);
            float bz1 = __ldg(&bias[col+1]);
            int row0 = bm + wm + mt*16 + g;
            if (row0 < M){
                float2 v = make_float2(acc[mt][nt][0] + bz0, acc[mt][nt][1] + bz1);
                *reinterpret_cast<float2*>(&C[(size_t)row0*N + col]) = v;
            }
            int row1 = row0 + 8;
            if (row1 < M){
                float2 v = make_float2(acc[mt][nt][2] + bz0, acc[mt][nt][3] + bz1);
                *reinterpret_cast<float2*>(&C[(size_t)row1*N + col]) = v;
            }
        }
    }
}

// =====================================================================
// Persistent GRU scan kernel (proven in R2). 128 blocks, 256 threads.
// Block owns 8 hidden cols; U slice tf32-rounded in SMEM for all steps.
// hi/lo tf32 split of h keeps the recurrence ~fp32 accurate.
// Stores hs tf32-pre-rounded (A operand of GEMM3).
// =====================================================================
#define SCAN_NBLK 128
#define U_LD 26
#define H_LD 1028
#define SCAN_SMEM ((HH*U_LD + BB*H_LD + 8*3*BB*8)*4)

__global__ __launch_bounds__(256, 1)
void gru_scan_kernel(const float* __restrict__ xproj,
                     const float* __restrict__ h0,
                     const float* __restrict__ U,
                     const float* __restrict__ brec)
{
    extern __shared__ float sm[];
    float* U_s = sm;
    float* h_s = sm + HH*U_LD;
    float* red = h_s + BB*H_LD;
    __shared__ unsigned bar_phase;

    const int tid  = threadIdx.x;
    const int lane = tid & 31;
    const int w    = tid >> 5;
    const int g    = lane >> 2;
    const int a    = lane & 3;
    const int j0   = blockIdx.x * 8;

    if (tid == 0) bar_phase = 0;

    for (int e = tid; e < HH*24; e += 256){
        int k = e / 24, c = e - k*24;
        int gate = c >> 3, jj = c & 7;
        float v = U[(size_t)k*H3 + gate*HH + j0 + jj];
        U_s[k*U_LD + c] = __uint_as_float(f2tf(v));
    }
    __syncthreads();

    for (int t = 0; t < TT; t++){
        const float* hsrc = (t == 0) ? h0 : g_h[(t-1) & 1];
        #pragma unroll
        for (int i = 0; i < 16; i++){
            int e = (i*256 + tid)*4;
            int b = e >> 10, k = e & 1023;
            float4 v = *reinterpret_cast<const float4*>(hsrc + e);
            *reinterpret_cast<float4*>(&h_s[b*H_LD + k]) = v;
        }
        __syncthreads();

        float c[3][4];
        #pragma unroll
        for (int nt = 0; nt < 3; nt++)
            #pragma unroll
            for (int q = 0; q < 4; q++) c[nt][q] = 0.f;

        const int kbase = w * 128;
        #pragma unroll 4
        for (int ks = 0; ks < 16; ks++){
            int k = kbase + ks*8;
            float f0 = h_s[(g    )*H_LD + k + a    ];
            float f1 = h_s[(g + 8)*H_LD + k + a    ];
            float f2 = h_s[(g    )*H_LD + k + a + 4];
            float f3 = h_s[(g + 8)*H_LD + k + a + 4];
            unsigned h0b = f2tf(f0), h1b = f2tf(f1), h2b = f2tf(f2), h3b = f2tf(f3);
            unsigned l0 = f2tf(f0 - __uint_as_float(h0b));
            unsigned l1 = f2tf(f1 - __uint_as_float(h1b));
            unsigned l2 = f2tf(f2 - __uint_as_float(h2b));
            unsigned l3 = f2tf(f3 - __uint_as_float(h3b));
            #pragma unroll
            for (int nt = 0; nt < 3; nt++){
                unsigned b0 = __float_as_uint(U_s[(k + a    )*U_LD + nt*8 + g]);
                unsigned b1 = __float_as_uint(U_s[(k + a + 4)*U_LD + nt*8 + g]);
                mma_tf32(c[nt], h0b, h1b, h2b, h3b, b0, b1);
                mma_tf32(c[nt], l0,  l1,  l2,  l3,  b0, b1);
            }
        }

        #pragma unroll
        for (int nt = 0; nt < 3; nt++){
            float* r = red + ((w*3 + nt)*BB)*8;
            r[(g    )*8 + 2*a    ] = c[nt][0];
            r[(g    )*8 + 2*a + 1] = c[nt][1];
            r[(g + 8)*8 + 2*a    ] = c[nt][2];
            r[(g + 8)*8 + 2*a + 1] = c[nt][3];
        }
        __syncthreads();

        if (tid < 128){
            int b = tid >> 3, jj = tid & 7;
            float rec[3];
            #pragma unroll
            for (int nt = 0; nt < 3; nt++){
                float s = __ldg(&brec[nt*HH + j0 + jj]);
                #pragma unroll
                for (int ww = 0; ww < 8; ww++)
                    s += red[((ww*3 + nt)*BB + b)*8 + jj];
                rec[nt] = s;
            }
            size_t base = (size_t)(b*TT + t) * H3;
            float xz = xproj[base +          j0 + jj];
            float xr = xproj[base +   HH   + j0 + jj];
            float xh = xproj[base + 2*HH   + j0 + jj];
            float z  = 1.f / (1.f + expf(-(xz + rec[0])));
            float r  = 1.f / (1.f + expf(-(xr + rec[1])));
            float hh = tanhf(xh + r * rec[2]);
            float hold = h_s[b*H_LD + j0 + jj];
            float hn = z * hold + (1.f - z) * hh;
            g_h[t & 1][b*HH + j0 + jj] = hn;
            g_hs[(size_t)(b*TT + t)*HH + j0 + jj] = __uint_as_float(f2tf(hn));
        }

        __syncthreads();
        if (tid == 0){
            unsigned exp = bar_phase ^ 1u;
            __threadfence();
            if (atomicAdd(&g_cnt, 1u) == SCAN_NBLK - 1){
                atomicExch(&g_cnt, 0u);
                __threadfence();
                atomicExch(&g_sense, exp);
            } else {
                while (atomicAdd(&g_sense, 0u) != exp) { __nanosleep(64); }
            }
            __threadfence();
            bar_phase = exp;
        }
        __syncthreads();
    }
}

// =====================================================================
// host launcher
// =====================================================================
extern "C" void kernel_launch(void* const* d_in, const int* in_sizes, int n_in,
                              void* d_out, int out_size)
{
    const int*   tok  = (const int*)  d_in[0];   // [16,250]
    const float* h0   = (const float*)d_in[1];   // [16,1024]
    const float* emb  = (const float*)d_in[2];   // [32000,512]
    const float* W    = (const float*)d_in[3];   // [512,3072]
    const float* U    = (const float*)d_in[4];   // [1024,3072]
    const float* b    = (const float*)d_in[5];   // [2,3072]
    const float* Wo   = (const float*)d_in[6];   // [1024,32000]
    const float* bo   = (const float*)d_in[7];   // [32000]
    float* out = (float*)d_out;                  // [16,250,32000] f32

    float* xproj; cudaGetSymbolAddress((void**)&xproj, g_xproj);
    float* hs;    cudaGetSymbolAddress((void**)&hs,    g_hs);
    float* embR;  cudaGetSymbolAddress((void**)&embR,  g_embR);
    float* WR;    cudaGetSymbolAddress((void**)&WR,    g_WR);
    float* WoR;   cudaGetSymbolAddress((void**)&WoR,   g_WoR);

    cudaFuncSetAttribute(gemm_pipe<true>,
        cudaFuncAttributeMaxDynamicSharedMemorySize, GEMM_SMEM);
    cudaFuncSetAttribute(gemm_pipe<false>,
        cudaFuncAttributeMaxDynamicSharedMemorySize, GEMM_SMEM);
    cudaFuncSetAttribute(gru_scan_kernel,
        cudaFuncAttributeMaxDynamicSharedMemorySize, SCAN_SMEM);

    // 0) tf32 pre-round of GEMM operands (cp.async cannot convert)
    round_tf32<<<1184, 256>>>(emb, embR, (size_t)VV*EE);
    round_tf32<<<1184, 256>>>(W,   WR,   (size_t)EE*H3);
    round_tf32<<<1184, 256>>>(Wo,  WoR,  (size_t)HH*VV);

    // 1) x_proj = gather(embR, tokens) @ WR + b[0]
    {
        dim3 grid((MM + BM - 1)/BM, H3/BN);   // 32 x 24
        gemm_pipe<true><<<grid, NTHR, GEMM_SMEM>>>(embR, WR, b, xproj, MM, H3, EE, tok);
    }

    // 2) GRU scan over T=250
    gru_scan_kernel<<<SCAN_NBLK, 256, SCAN_SMEM>>>(xproj, h0, U, b + H3);

    // 3) logits = hs @ WoR + bo
    {
        dim3 grid((MM + BM - 1)/BM, VV/BN);   // 32 x 250
        gemm_pipe<false><<<grid, NTHR, GEMM_SMEM>>>(hs, WoR, bo, out, MM, VV, HH, nullptr);
    }
}

// round 11
// speedup vs baseline: 1.4845x; 1.2771x over previous
#include <cuda_runtime.h>
#include <cuda_fp16.h>
#include <cstdint>

// ---------------- problem constants ----------------
#define BB 16
#define TT 250
#define EE 512
#define HH 1024
#define VV 32000
#define H3 3072
#define MM (BB*TT)          // 4000

// ---------------- scratch (static device memory; no allocations) ----------------
__device__ __align__(16) float  g_xproj[MM*H3];            // [4000,3072] fp32
__device__ __align__(16) __half g_hsH[(size_t)MM*HH];      // [4000,1024] fp16
__device__ __align__(16) float  g_h[2][BB*HH];             // hidden state (fp32)
__device__ __align__(16) __half g_embH[(size_t)VV*EE];     // emb fp16
__device__ __align__(16) __half g_WTH [(size_t)H3*EE];     // W^T  [3072,512] fp16
__device__ __align__(16) __half g_WoTH[(size_t)VV*HH];     // Wo^T [32000,1024] fp16
__device__ unsigned g_cnt = 0;
__device__ unsigned g_sense = 0;

// ---------------- helpers ----------------
__device__ __forceinline__ unsigned f2tf(float f){
    unsigned u; asm("cvt.rna.tf32.f32 %0, %1;" : "=r"(u) : "f"(f)); return u;
}
__device__ __forceinline__ void mma_tf32(float* c,
    unsigned a0, unsigned a1, unsigned a2, unsigned a3,
    unsigned b0, unsigned b1){
    asm volatile("mma.sync.aligned.m16n8k8.row.col.f32.tf32.tf32.f32 "
        "{%0,%1,%2,%3},{%4,%5,%6,%7},{%8,%9},{%0,%1,%2,%3};"
        : "+f"(c[0]), "+f"(c[1]), "+f"(c[2]), "+f"(c[3])
        : "r"(a0), "r"(a1), "r"(a2), "r"(a3), "r"(b0), "r"(b1));
}
__device__ __forceinline__ void mma_f16(float* c,
    unsigned a0, unsigned a1, unsigned a2, unsigned a3,
    unsigned b0, unsigned b1){
    asm volatile("mma.sync.aligned.m16n8k16.row.col.f32.f16.f16.f32 "
        "{%0,%1,%2,%3},{%4,%5,%6,%7},{%8,%9},{%0,%1,%2,%3};"
        : "+f"(c[0]), "+f"(c[1]), "+f"(c[2]), "+f"(c[3])
        : "r"(a0), "r"(a1), "r"(a2), "r"(a3), "r"(b0), "r"(b1));
}
__device__ __forceinline__ uint32_t smem_u32(const void* p){
    uint32_t a;
    asm("{ .reg .u64 t; cvta.to.shared.u64 t, %1; cvt.u32.u64 %0, t; }" : "=r"(a) : "l"(p));
    return a;
}
__device__ __forceinline__ void cpa16(uint32_t dst, const void* src, int sz){
    asm volatile("cp.async.cg.shared.global [%0], [%1], 16, %2;" :: "r"(dst), "l"(src), "r"(sz));
}
__device__ __forceinline__ void cpa_commit(){ asm volatile("cp.async.commit_group;"); }
template<int N> __device__ __forceinline__ void cpa_wait(){ asm volatile("cp.async.wait_group %0;" :: "n"(N)); }

// =====================================================================
// fp32 -> fp16 elementwise convert (rn).  n % 4 == 0.
// =====================================================================
__global__ void to_half(const float* __restrict__ src, __half* __restrict__ dst, size_t n)
{
    size_t stride = (size_t)gridDim.x * blockDim.x * 4;
    for (size_t i = ((size_t)blockIdx.x * blockDim.x + threadIdx.x) * 4; i < n; i += stride){
        float4 v = *reinterpret_cast<const float4*>(src + i);
        __half2 h0 = __floats2half2_rn(v.x, v.y);
        __half2 h1 = __floats2half2_rn(v.z, v.w);
        uint2 o;
        o.x = *reinterpret_cast<unsigned*>(&h0);
        o.y = *reinterpret_cast<unsigned*>(&h1);
        *reinterpret_cast<uint2*>(dst + i) = o;
    }
}

// =====================================================================
// fp32 -> fp16 transpose-convert: dst[c][r] = h(src[r][c]). Dims % 32 == 0.
// =====================================================================
__global__ void trans_half(const float* __restrict__ src, __half* __restrict__ dst,
                           int R, int C)
{
    __shared__ float t[32][33];
    int cb = blockIdx.x * 32, rb = blockIdx.y * 32;
    #pragma unroll
    for (int i = 0; i < 4; i++){
        int r = rb + threadIdx.y + i*8;
        t[threadIdx.y + i*8][threadIdx.x] = src[(size_t)r*C + cb + threadIdx.x];
    }
    __syncthreads();
    #pragma unroll
    for (int i = 0; i < 4; i++){
        int c = cb + threadIdx.y + i*8;
        dst[(size_t)c*R + rb + threadIdx.x] = __float2half_rn(t[threadIdx.x][threadIdx.y + i*8]);
    }
}

// =====================================================================
// fp16 3-stage cp.async pipelined GEMM, 2 blocks/SM:
//   C[M,N] = A[M,K] @ BT[N,K]^T + bias[N]   (A,BT fp16; C,bias fp32)
// BM=128, BN=128, BK=32 (halves), 256 threads, 8 warps (2x4),
// warp tile 64x32, mma.m16n8k16. SMEM rows padded to 80B:
// conflict-free b32 fragment reads AND phase-conflict-free 16B writes
// (c-major chunk mapping). Crossbar bytes per k-tile halved vs fp32.
// GATHER: A row m comes from A[tokens[m]] (embedding, K = E).
// =====================================================================
#define BM 128
#define BN 128
#define BK 32
#define NTHR 256
#define ROW_B 80                              // 64B data + 16B pad
#define STG_B (2*BM*ROW_B)                    // 20480 B per stage (A+B)
#define GEMM_SMEM (3*STG_B)                   // 61440 B (2 blocks/SM)

template<bool GATHER>
__global__ __launch_bounds__(NTHR, 2)
void gemm_h(const __half* __restrict__ A, const __half* __restrict__ BT,
            const float* __restrict__ bias, float* __restrict__ C,
            int M, int N, int K, const int* __restrict__ tokens)
{
    extern __shared__ char smc[];
    const uint32_t sb = smem_u32(smc);

    const int tid  = threadIdx.x;
    const int lane = tid & 31;
    const int w    = tid >> 5;         // 0..7
    const int g    = lane >> 2;        // 0..7
    const int a    = lane & 3;         // 0..3
    const int wm   = (w >> 2) * 64;    // 2 row-groups of 64
    const int wn   = (w & 3) * 32;     // 4 col-groups of 32

    const int bm = blockIdx.x * BM;
    const int bn = blockIdx.y * BN;
    const int KT = K / BK;

    float acc[4][4][4];
    #pragma unroll
    for (int i = 0; i < 4; i++)
        #pragma unroll
        for (int j = 0; j < 4; j++)
            #pragma unroll
            for (int q = 0; q < 4; q++) acc[i][j][q] = 0.f;

    // chunk mapping (write-conflict-free): idx in [0,512):
    //   row = (idx & 7) | ((idx >> 5) << 3),  c = (idx >> 3) & 3
    // each warp-octet writes 8 distinct rows at the same chunk c.
    auto issue = [&](int kt, int s){
        const uint32_t Ab = sb + s*STG_B;
        const uint32_t Bb = Ab + BM*ROW_B;
        const int k0 = kt * BK;                    // half index
        #pragma unroll
        for (int i = 0; i < 2; i++){
            int idx = tid + i*NTHR;                // 0..511
            int row = (idx & 7) | ((idx >> 5) << 3);
            int c   = (idx >> 3) & 3;
            int m = bm + row;
            const __half* src = A;
            int sz = 0;
            if (GATHER){
                if (m < M){ int tok = __ldg(&tokens[m]);
                            src = A + (size_t)tok*K + k0 + c*8; sz = 16; }
            } else {
                if (m < M){ src = A + (size_t)m*K + k0 + c*8; sz = 16; }
            }
            cpa16(Ab + row*ROW_B + c*16, src, sz);
        }
        #pragma unroll
        for (int i = 0; i < 2; i++){
            int idx = tid + i*NTHR;
            int row = (idx & 7) | ((idx >> 5) << 3);
            int c   = (idx >> 3) & 3;
            const __half* src = BT + (size_t)(bn + row)*K + k0 + c*8;
            cpa16(Bb + row*ROW_B + c*16, src, 16);
        }
    };

    auto compute = [&](int s){
        const char* Ab = smc + s*STG_B;
        const char* Bb = Ab + BM*ROW_B;
        #pragma unroll
        for (int ks = 0; ks < 2; ks++){
            const int kb = ks*32 + 4*a;            // byte offset in row
            unsigned Af[4][4];
            #pragma unroll
            for (int mt = 0; mt < 4; mt++){
                const char* ap  = Ab + (wm + mt*16 + g)*ROW_B + kb;
                const char* ap8 = ap + 8*ROW_B;
                Af[mt][0] = *reinterpret_cast<const unsigned*>(ap);
                Af[mt][1] = *reinterpret_cast<const unsigned*>(ap8);
                Af[mt][2] = *reinterpret_cast<const unsigned*>(ap  + 16);
                Af[mt][3] = *reinterpret_cast<const unsigned*>(ap8 + 16);
            }
            #pragma unroll
            for (int nt = 0; nt < 4; nt++){
                const char* bp = Bb + (wn + nt*8 + g)*ROW_B + kb;
                unsigned b0 = *reinterpret_cast<const unsigned*>(bp);
                unsigned b1 = *reinterpret_cast<const unsigned*>(bp + 16);
                #pragma unroll
                for (int mt = 0; mt < 4; mt++)
                    mma_f16(acc[mt][nt], Af[mt][0],Af[mt][1],Af[mt][2],Af[mt][3], b0, b1);
            }
        }
    };

    // ---- 3-stage pipeline, ONE barrier per k-tile (proven in R10) ----
    issue(0, 0); cpa_commit();
    issue(1, 1); cpa_commit();
    int s_c = 0, s_i = 2;
    for (int kt = 0; kt < KT; kt++){
        cpa_wait<1>();
        __syncthreads();
        if (kt + 2 < KT) issue(kt + 2, s_i);
        cpa_commit();
        compute(s_c);
        s_c = (s_c == 2) ? 0 : s_c + 1;
        s_i = (s_i == 2) ? 0 : s_i + 1;
    }

    // ---- epilogue: +bias, write float2 pairs ----
    #pragma unroll
    for (int mt = 0; mt < 4; mt++){
        #pragma unroll
        for (int nt = 0; nt < 4; nt++){
            int col  = bn + wn + nt*8 + 2*a;
            float bz0 = __ldg(&bias[col]);
            float bz1 = __ldg(&bias[col+1]);
            int row0 = bm + wm + mt*16 + g;
            if (row0 < M){
                float2 v = make_float2(acc[mt][nt][0] + bz0, acc[mt][nt][1] + bz1);
                *reinterpret_cast<float2*>(&C[(size_t)row0*N + col]) = v;
            }
            int row1 = row0 + 8;
            if (row1 < M){
                float2 v = make_float2(acc[mt][nt][2] + bz0, acc[mt][nt][3] + bz1);
                *reinterpret_cast<float2*>(&C[(size_t)row1*N + col]) = v;
            }
        }
    }
}

// =====================================================================
// Persistent GRU scan kernel (proven). 128 blocks, 256 threads.
// Block owns 8 hidden cols; U slice tf32-rounded in SMEM for all steps.
// hi/lo tf32 split of h keeps the recurrence ~fp32 accurate.
// Stores hs as fp16 (A operand of GEMM3).
// =====================================================================
#define SCAN_NBLK 128
#define U_LD 26
#define H_LD 1028
#define SCAN_SMEM ((HH*U_LD + BB*H_LD + 8*3*BB*8)*4)

__global__ __launch_bounds__(256, 1)
void gru_scan_kernel(const float* __restrict__ xproj,
                     const float* __restrict__ h0,
                     const float* __restrict__ U,
                     const float* __restrict__ brec)
{
    extern __shared__ float sm[];
    float* U_s = sm;
    float* h_s = sm + HH*U_LD;
    float* red = h_s + BB*H_LD;
    __shared__ unsigned bar_phase;

    const int tid  = threadIdx.x;
    const int lane = tid & 31;
    const int w    = tid >> 5;
    const int g    = lane >> 2;
    const int a    = lane & 3;
    const int j0   = blockIdx.x * 8;

    if (tid == 0) bar_phase = 0;

    for (int e = tid; e < HH*24; e += 256){
        int k = e / 24, c = e - k*24;
        int gate = c >> 3, jj = c & 7;
        float v = U[(size_t)k*H3 + gate*HH + j0 + jj];
        U_s[k*U_LD + c] = __uint_as_float(f2tf(v));
    }
    __syncthreads();

    for (int t = 0; t < TT; t++){
        const float* hsrc = (t == 0) ? h0 : g_h[(t-1) & 1];
        #pragma unroll
        for (int i = 0; i < 16; i++){
            int e = (i*256 + tid)*4;
            int b = e >> 10, k = e & 1023;
            float4 v = *reinterpret_cast<const float4*>(hsrc + e);
            *reinterpret_cast<float4*>(&h_s[b*H_LD + k]) = v;
        }
        __syncthreads();

        float c[3][4];
        #pragma unroll
        for (int nt = 0; nt < 3; nt++)
            #pragma unroll
            for (int q = 0; q < 4; q++) c[nt][q] = 0.f;

        const int kbase = w * 128;
        #pragma unroll 4
        for (int ks = 0; ks < 16; ks++){
            int k = kbase + ks*8;
            float f0 = h_s[(g    )*H_LD + k + a    ];
            float f1 = h_s[(g + 8)*H_LD + k + a    ];
            float f2 = h_s[(g    )*H_LD + k + a + 4];
            float f3 = h_s[(g + 8)*H_LD + k + a + 4];
            unsigned h0b = f2tf(f0), h1b = f2tf(f1), h2b = f2tf(f2), h3b = f2tf(f3);
            unsigned l0 = f2tf(f0 - __uint_as_float(h0b));
            unsigned l1 = f2tf(f1 - __uint_as_float(h1b));
            unsigned l2 = f2tf(f2 - __uint_as_float(h2b));
            unsigned l3 = f2tf(f3 - __uint_as_float(h3b));
            #pragma unroll
            for (int nt = 0; nt < 3; nt++){
                unsigned b0 = __float_as_uint(U_s[(k + a    )*U_LD + nt*8 + g]);
                unsigned b1 = __float_as_uint(U_s[(k + a + 4)*U_LD + nt*8 + g]);
                mma_tf32(c[nt], h0b, h1b, h2b, h3b, b0, b1);
                mma_tf32(c[nt], l0,  l1,  l2,  l3,  b0, b1);
            }
        }

        #pragma unroll
        for (int nt = 0; nt < 3; nt++){
            float* r = red + ((w*3 + nt)*BB)*8;
            r[(g    )*8 + 2*a    ] = c[nt][0];
            r[(g    )*8 + 2*a + 1] = c[nt][1];
            r[(g + 8)*8 + 2*a    ] = c[nt][2];
            r[(g + 8)*8 + 2*a + 1] = c[nt][3];
        }
        __syncthreads();

        if (tid < 128){
            int b = tid >> 3, jj = tid & 7;
            float rec[3];
            #pragma unroll
            for (int nt = 0; nt < 3; nt++){
                float s = __ldg(&brec[nt*HH + j0 + jj]);
                #pragma unroll
                for (int ww = 0; ww < 8; ww++)
                    s += red[((ww*3 + nt)*BB + b)*8 + jj];
                rec[nt] = s;
            }
            size_t base = (size_t)(b*TT + t) * H3;
            float xz = xproj[base +          j0 + jj];
            float xr = xproj[base +   HH   + j0 + jj];
            float xh = xproj[base + 2*HH   + j0 + jj];
            float z  = 1.f / (1.f + expf(-(xz + rec[0])));
            float r  = 1.f / (1.f + expf(-(xr + rec[1])));
            float hh = tanhf(xh + r * rec[2]);
            float hold = h_s[b*H_LD + j0 + jj];
            float hn = z * hold + (1.f - z) * hh;
            g_h[t & 1][b*HH + j0 + jj] = hn;
            g_hsH[(size_t)(b*TT + t)*HH + j0 + jj] = __float2half_rn(hn);
        }

        __syncthreads();
        if (tid == 0){
            unsigned exp = bar_phase ^ 1u;
            __threadfence();
            if (atomicAdd(&g_cnt, 1u) == SCAN_NBLK - 1){
                atomicExch(&g_cnt, 0u);
                __threadfence();
                atomicExch(&g_sense, exp);
            } else {
                while (atomicAdd(&g_sense, 0u) != exp) { __nanosleep(64); }
            }
            __threadfence();
            bar_phase = exp;
        }
        __syncthreads();
    }
}

// =====================================================================
// host launcher
// =====================================================================
extern "C" void kernel_launch(void* const* d_in, const int* in_sizes, int n_in,
                              void* d_out, int out_size)
{
    const int*   tok  = (const int*)  d_in[0];   // [16,250]
    const float* h0   = (const float*)d_in[1];   // [16,1024]
    const float* emb  = (const float*)d_in[2];   // [32000,512]
    const float* W    = (const float*)d_in[3];   // [512,3072]
    const float* U    = (const float*)d_in[4];   // [1024,3072]
    const float* b    = (const float*)d_in[5];   // [2,3072]
    const float* Wo   = (const float*)d_in[6];   // [1024,32000]
    const float* bo   = (const float*)d_in[7];   // [32000]
    float* out = (float*)d_out;                  // [16,250,32000] f32

    float*  xproj; cudaGetSymbolAddress((void**)&xproj, g_xproj);
    __half* hsH;   cudaGetSymbolAddress((void**)&hsH,   g_hsH);
    __half* embH;  cudaGetSymbolAddress((void**)&embH,  g_embH);
    __half* WTH;   cudaGetSymbolAddress((void**)&WTH,   g_WTH);
    __half* WoTH;  cudaGetSymbolAddress((void**)&WoTH,  g_WoTH);

    cudaFuncSetAttribute(gemm_h<true>,
        cudaFuncAttributeMaxDynamicSharedMemorySize, GEMM_SMEM);
    cudaFuncSetAttribute(gemm_h<false>,
        cudaFuncAttributeMaxDynamicSharedMemorySize, GEMM_SMEM);
    cudaFuncSetAttribute(gru_scan_kernel,
        cudaFuncAttributeMaxDynamicSharedMemorySize, SCAN_SMEM);

    // 0) fp16 conversion / transposition of GEMM operands
    to_half<<<1184, 256>>>(emb, embH, (size_t)VV*EE);
    {
        dim3 tb(32, 8);
        trans_half<<<dim3(H3/32, EE/32), tb>>>(W,  WTH,  EE, H3);   // -> [3072,512]
        trans_half<<<dim3(VV/32, HH/32), tb>>>(Wo, WoTH, HH, VV);   // -> [32000,1024]
    }

    // 1) x_proj = gather(embH, tokens) @ W + b[0]
    {
        dim3 grid((MM + BM - 1)/BM, H3/BN);   // 32 x 24
        gemm_h<true><<<grid, NTHR, GEMM_SMEM>>>(embH, WTH, b, xproj, MM, H3, EE, tok);
    }

    // 2) GRU scan over T=250
    gru_scan_kernel<<<SCAN_NBLK, 256, SCAN_SMEM>>>(xproj, h0, U, b + H3);

    // 3) logits = hs @ Wo + bo
    {
        dim3 grid((MM + BM - 1)/BM, VV/BN);   // 32 x 250
        gemm_h<false><<<grid, NTHR, GEMM_SMEM>>>(hsH, WoTH, bo, out, MM, VV, HH, nullptr);
    }
}